// round 8
// baseline (speedup 1.0000x reference)
#include <cuda_runtime.h>
#include <cuda_fp16.h>
#include <math.h>
#include <stdint.h>

#define BB 8192
#define DD 768
#define GH 384
#define EE 8
#define HH 3072
#define LN_EPS 1e-5f

// ---------------- scratch (static device globals) ----------------
__device__ __half g_ht [(size_t)BB * DD];          // LN output, half hi
__device__ __half g_htl[(size_t)BB * DD];          // LN output, half lo
__device__ float  g_g1 [(size_t)BB * GH];          // gating hidden (fp32-faithful)
__device__ __half g_hid[(size_t)EE * BB * HH];     // expert hidden, half
__device__ __half g_w1t[(size_t)EE * HH * DD];     // ew1^T [e][H][D], half (K-major)
__device__ __half g_w2t[(size_t)EE * DD * HH];     // ew2^T [e][D][H], half (K-major)
__device__ __half g_gw1h[(size_t)GH * DD];         // gw1^T hi [Gh][D]
__device__ __half g_gw1l[(size_t)GH * DD];         // gw1^T lo [Gh][D]
__device__ float  g_w  [(size_t)BB * 2];
__device__ int    g_i  [(size_t)BB * 2];

// ---------------- helpers ----------------
__device__ __forceinline__ float gelu_erf(float x) {
    return 0.5f * x * (1.0f + erff(x * 0.70710678118654752f));
}
__device__ __forceinline__ uint32_t s2u(const void* p) {
    uint32_t a;
    asm("{ .reg .u64 t; cvta.to.shared.u64 t, %1; cvt.u32.u64 %0, t; }" : "=r"(a) : "l"(p));
    return a;
}

#define SWZ(off) ((uint32_t)(off) ^ (((uint32_t)(off) >> 3) & 0x70u))

#define CPA16(dst, src) \
    asm volatile("cp.async.cg.shared.global [%0], [%1], 16;" :: "r"(dst), "l"(src))
#define CPCOMMIT() asm volatile("cp.async.commit_group;" ::: "memory")
#define CPWAIT0()  asm volatile("cp.async.wait_group 0;" ::: "memory")
#define CPWAIT1()  asm volatile("cp.async.wait_group 1;" ::: "memory")

#define LDSM4(r, addr) \
    asm volatile("ldmatrix.sync.aligned.m8n8.x4.shared.b16 {%0,%1,%2,%3}, [%4];" \
        : "=r"((r)[0]), "=r"((r)[1]), "=r"((r)[2]), "=r"((r)[3]) : "r"(addr))

__device__ __forceinline__ void mma_f16(float c[4], const uint32_t a[4],
                                        uint32_t b0, uint32_t b1) {
    asm volatile(
        "mma.sync.aligned.m16n8k16.row.col.f32.f16.f16.f32 "
        "{%0,%1,%2,%3}, {%4,%5,%6,%7}, {%8,%9}, {%0,%1,%2,%3};"
        : "+f"(c[0]), "+f"(c[1]), "+f"(c[2]), "+f"(c[3])
        : "r"(a[0]), "r"(a[1]), "r"(a[2]), "r"(a[3]), "r"(b0), "r"(b1));
}

// ---------------------------------------------------------------------------
// K1: LayerNorm -> g_ht (hi) + g_htl (lo)
// ---------------------------------------------------------------------------
__global__ void ln_kernel(const float* __restrict__ x,
                          const float* __restrict__ gamma,
                          const float* __restrict__ beta) {
    int b = blockIdx.x;
    const float* row = x + (size_t)b * DD;
    float s = 0.f, ss = 0.f;
    for (int d = threadIdx.x; d < DD; d += blockDim.x) {
        float v = row[d];
        s += v; ss += v * v;
    }
    #pragma unroll
    for (int o = 16; o; o >>= 1) {
        s  += __shfl_xor_sync(0xffffffffu, s, o);
        ss += __shfl_xor_sync(0xffffffffu, ss, o);
    }
    __shared__ float rs[8], rss[8];
    int w = threadIdx.x >> 5, l = threadIdx.x & 31;
    if (l == 0) { rs[w] = s; rss[w] = ss; }
    __syncthreads();
    if (w == 0) {
        s  = (l < (blockDim.x >> 5)) ? rs[l]  : 0.f;
        ss = (l < (blockDim.x >> 5)) ? rss[l] : 0.f;
        #pragma unroll
        for (int o = 4; o; o >>= 1) {
            s  += __shfl_xor_sync(0xffffffffu, s, o);
            ss += __shfl_xor_sync(0xffffffffu, ss, o);
        }
        if (l == 0) { rs[0] = s; rss[0] = ss; }
    }
    __syncthreads();
    float mu  = rs[0] * (1.0f / DD);
    float var = rss[0] * (1.0f / DD) - mu * mu;
    float inv = rsqrtf(var + LN_EPS);
    for (int d = threadIdx.x; d < DD; d += blockDim.x) {
        float v = (row[d] - mu) * inv * gamma[d] + beta[d];
        __half hi = __float2half_rn(v);
        g_ht [(size_t)b * DD + d] = hi;
        g_htl[(size_t)b * DD + d] = __float2half_rn(v - __half2float(hi));
    }
}

// ---------------------------------------------------------------------------
// Weight transpose + fp32->half: src fp32 [e][R][C] -> dst half [e][C][R]
// ---------------------------------------------------------------------------
__global__ void transpose_h_kernel(const float* __restrict__ src,
                                   __half* __restrict__ dst, int R, int C) {
    __shared__ float t[32][33];
    int e = blockIdx.z;
    src += (size_t)e * R * C;
    dst += (size_t)e * R * C;
    int c0 = blockIdx.x * 32, r0 = blockIdx.y * 32;
    #pragma unroll
    for (int j = 0; j < 32; j += 8)
        t[threadIdx.y + j][threadIdx.x] =
            src[(size_t)(r0 + threadIdx.y + j) * C + c0 + threadIdx.x];
    __syncthreads();
    #pragma unroll
    for (int j = 0; j < 32; j += 8)
        dst[(size_t)(c0 + threadIdx.y + j) * R + r0 + threadIdx.x] =
            __float2half_rn(t[threadIdx.x][threadIdx.y + j]);
}

// Transpose + hi/lo split: src fp32 [R][C] -> hi/lo half [C][R]
__global__ void transpose_split_kernel(const float* __restrict__ src,
                                       __half* __restrict__ dh,
                                       __half* __restrict__ dl, int R, int C) {
    __shared__ float t[32][33];
    int c0 = blockIdx.x * 32, r0 = blockIdx.y * 32;
    #pragma unroll
    for (int j = 0; j < 32; j += 8)
        t[threadIdx.y + j][threadIdx.x] =
            src[(size_t)(r0 + threadIdx.y + j) * C + c0 + threadIdx.x];
    __syncthreads();
    #pragma unroll
    for (int j = 0; j < 32; j += 8) {
        float v = t[threadIdx.x][threadIdx.y + j];
        __half hi = __float2half_rn(v);
        size_t idx = (size_t)(c0 + threadIdx.y + j) * R + r0 + threadIdx.x;
        dh[idx] = hi;
        dl[idx] = __float2half_rn(v - __half2float(hi));
    }
}

// ---------------------------------------------------------------------------
// Split-fp16 gate GEMM: g1 = gelu((Ah+Al) @ (Bh+Bl)^T + gb1), fp32-faithful.
// M=BB, N=GH, K=DD. CTA 128x128, BK=64, 3-stage. acc = AhBh + AhBl + AlBh.
// ---------------------------------------------------------------------------
__global__ __launch_bounds__(256, 1)
void hgemm_gate(const __half* __restrict__ Ah, const __half* __restrict__ Al,
                const __half* __restrict__ Bh, const __half* __restrict__ Bl,
                const float* __restrict__ bias, float* __restrict__ C) {
    constexpr int K = DD, BK = 64, NIT = K / BK;
    constexpr int TB = 128 * 128;            // 16 KB per tile
    constexpr int STAGE_BYTES = 4 * TB;      // 64 KB
    constexpr int STAGES = 3;

    extern __shared__ char smem[];
    const int n0 = blockIdx.x * 128;
    const int m0 = blockIdx.y * 128;

    const int tid   = threadIdx.x;
    const int warp  = tid >> 5;
    const int lane  = tid & 31;
    const int warpM = warp >> 2;
    const int warpN = warp & 3;

    const uint32_t sbase = s2u(smem);

    auto load_stage = [&](int s, int k0) {
        uint32_t aH = sbase + (uint32_t)s * STAGE_BYTES;
        uint32_t aL = aH + TB, bH = aH + 2 * TB, bL = aH + 3 * TB;
        #pragma unroll
        for (int t = 0; t < 4; t++) {
            int id = tid + t * 256;
            int row = id >> 3, c = id & 7;
            uint32_t o = SWZ(row * 128 + c * 16);
            CPA16(aH + o, Ah + (size_t)(m0 + row) * K + k0 + c * 8);
            CPA16(aL + o, Al + (size_t)(m0 + row) * K + k0 + c * 8);
            CPA16(bH + o, Bh + (size_t)(n0 + row) * K + k0 + c * 8);
            CPA16(bL + o, Bl + (size_t)(n0 + row) * K + k0 + c * 8);
        }
    };

    load_stage(0, 0);   CPCOMMIT();
    load_stage(1, BK);  CPCOMMIT();

    float acc[4][4][4] = {};

    for (int i = 0; i < NIT; i++) {
        if (i + 1 < NIT) { CPWAIT1(); } else { CPWAIT0(); }
        __syncthreads();
        if (i + 2 < NIT) { load_stage((i + 2) % STAGES, (i + 2) * BK); CPCOMMIT(); }

        const uint32_t aH = sbase + (uint32_t)(i % STAGES) * STAGE_BYTES;
        const uint32_t aL = aH + TB, bH = aH + 2 * TB, bL = aH + 3 * TB;

        #pragma unroll
        for (int ks = 0; ks < 4; ks++) {
            uint32_t afh[4][4], afl[4][4], bfh[2][4], bfl[2][4];
            const int c = ks * 2 + (lane >> 4);
            #pragma unroll
            for (int ii = 0; ii < 4; ii++) {
                int row = warpM * 64 + ii * 16 + (lane & 15);
                uint32_t o = SWZ(row * 128 + c * 16);
                LDSM4(afh[ii], aH + o);
                LDSM4(afl[ii], aL + o);
            }
            #pragma unroll
            for (int jp = 0; jp < 2; jp++) {
                int row = warpN * 32 + jp * 16 + (lane & 15);
                uint32_t o = SWZ(row * 128 + c * 16);
                LDSM4(bfh[jp], bH + o);
                LDSM4(bfl[jp], bL + o);
            }
            #pragma unroll
            for (int ii = 0; ii < 4; ii++) {
                #pragma unroll
                for (int jp = 0; jp < 2; jp++) {
                    mma_f16(acc[ii][jp * 2 + 0], afh[ii], bfh[jp][0], bfh[jp][2]);
                    mma_f16(acc[ii][jp * 2 + 1], afh[ii], bfh[jp][1], bfh[jp][3]);
                    mma_f16(acc[ii][jp * 2 + 0], afh[ii], bfl[jp][0], bfl[jp][2]);
                    mma_f16(acc[ii][jp * 2 + 1], afh[ii], bfl[jp][1], bfl[jp][3]);
                    mma_f16(acc[ii][jp * 2 + 0], afl[ii], bfh[jp][0], bfh[jp][2]);
                    mma_f16(acc[ii][jp * 2 + 1], afl[ii], bfh[jp][1], bfh[jp][3]);
                }
            }
        }
    }

    const int r  = lane >> 2;
    const int c2 = (lane & 3) * 2;
    #pragma unroll
    for (int ii = 0; ii < 4; ii++) {
        int row0 = m0 + warpM * 64 + ii * 16 + r;
        int row1 = row0 + 8;
        #pragma unroll
        for (int j = 0; j < 4; j++) {
            int gcol = n0 + warpN * 32 + j * 8 + c2;
            float b0 = bias[gcol], b1 = bias[gcol + 1];
            float v0 = gelu_erf(acc[ii][j][0] + b0);
            float v1 = gelu_erf(acc[ii][j][1] + b1);
            float v2 = gelu_erf(acc[ii][j][2] + b0);
            float v3 = gelu_erf(acc[ii][j][3] + b1);
            *(float2*)(C + (size_t)row0 * GH + gcol) = make_float2(v0, v1);
            *(float2*)(C + (size_t)row1 * GH + gcol) = make_float2(v2, v3);
        }
    }
}

// ---------------------------------------------------------------------------
// Expert fp16 GEMM: CTA 128x256, warp tile 64x64, BK=64, 3-stage cp.async.
// A half [e][M][K] row-major; Bt half [e][N][K] K-major. fp32 accumulate.
// ---------------------------------------------------------------------------
template <int K, int N, bool GELU, bool EOUT>
__global__ __launch_bounds__(256, 1)
void hgemm256(const __half* __restrict__ A, size_t aStride,
              const __half* __restrict__ Bt,
              const float* __restrict__ bias,
              void* __restrict__ Cout) {
    constexpr int BK = 64;
    constexpr int NIT = K / BK;
    constexpr int ABYTES = 128 * 128;        // 16 KB
    constexpr int BBYTES = 256 * 128;        // 32 KB
    constexpr int STAGE_BYTES = ABYTES + BBYTES;
    constexpr int STAGES = 3;

    extern __shared__ char smem[];
    const int e  = blockIdx.z;
    const int n0 = blockIdx.x * 256;
    const int m0 = blockIdx.y * 128;
    A    += (size_t)e * aStride;
    Bt   += (size_t)e * (size_t)N * K;
    bias += (size_t)e * N;

    const int tid   = threadIdx.x;
    const int warp  = tid >> 5;
    const int lane  = tid & 31;
    const int warpM = warp >> 2;             // 0..1 -> *64
    const int warpN = warp & 3;              // 0..3 -> *64

    const uint32_t sbase = s2u(smem);

    auto load_stage = [&](int s, int k0) {
        uint32_t aB = sbase + (uint32_t)s * STAGE_BYTES;
        uint32_t bB = aB + ABYTES;
        #pragma unroll
        for (int t = 0; t < 4; t++) {
            int id = tid + t * 256;
            int row = id >> 3, c = id & 7;
            CPA16(aB + SWZ(row * 128 + c * 16), A + (size_t)(m0 + row) * K + k0 + c * 8);
        }
        #pragma unroll
        for (int t = 0; t < 8; t++) {
            int id = tid + t * 256;
            int row = id >> 3, c = id & 7;
            CPA16(bB + SWZ(row * 128 + c * 16), Bt + (size_t)(n0 + row) * K + k0 + c * 8);
        }
    };

    load_stage(0, 0);   CPCOMMIT();
    load_stage(1, BK);  CPCOMMIT();

    float acc[4][8][4] = {};

    for (int i = 0; i < NIT; i++) {
        if (i + 1 < NIT) { CPWAIT1(); } else { CPWAIT0(); }
        __syncthreads();
        if (i + 2 < NIT) { load_stage((i + 2) % STAGES, (i + 2) * BK); CPCOMMIT(); }

        const uint32_t aB = sbase + (uint32_t)(i % STAGES) * STAGE_BYTES;
        const uint32_t bB = aB + ABYTES;

        #pragma unroll
        for (int ks = 0; ks < 4; ks++) {
            uint32_t afr[4][4], bfr[4][4];
            const int c = ks * 2 + (lane >> 4);
            #pragma unroll
            for (int ii = 0; ii < 4; ii++) {
                int row = warpM * 64 + ii * 16 + (lane & 15);
                LDSM4(afr[ii], aB + SWZ(row * 128 + c * 16));
            }
            #pragma unroll
            for (int jp = 0; jp < 4; jp++) {
                int row = warpN * 64 + jp * 16 + (lane & 15);
                LDSM4(bfr[jp], bB + SWZ(row * 128 + c * 16));
            }
            #pragma unroll
            for (int ii = 0; ii < 4; ii++) {
                #pragma unroll
                for (int jp = 0; jp < 4; jp++) {
                    mma_f16(acc[ii][jp * 2 + 0], afr[ii], bfr[jp][0], bfr[jp][2]);
                    mma_f16(acc[ii][jp * 2 + 1], afr[ii], bfr[jp][1], bfr[jp][3]);
                }
            }
        }
    }

    // epilogue
    const int r  = lane >> 2;
    const int c2 = (lane & 3) * 2;
    #pragma unroll
    for (int ii = 0; ii < 4; ii++) {
        int row0 = m0 + warpM * 64 + ii * 16 + r;
        int row1 = row0 + 8;
        #pragma unroll
        for (int j = 0; j < 8; j++) {
            int gcol = n0 + warpN * 64 + j * 8 + c2;
            float b0 = bias[gcol], b1 = bias[gcol + 1];
            float v0 = acc[ii][j][0] + b0;
            float v1 = acc[ii][j][1] + b1;
            float v2 = acc[ii][j][2] + b0;
            float v3 = acc[ii][j][3] + b1;
            if (GELU) {
                v0 = gelu_erf(v0); v1 = gelu_erf(v1);
                v2 = gelu_erf(v2); v3 = gelu_erf(v3);
            }
            if (EOUT) {
                float* C = (float*)Cout;
                *(float2*)(C + ((size_t)row0 * EE + e) * DD + gcol) = make_float2(v0, v1);
                *(float2*)(C + ((size_t)row1 * EE + e) * DD + gcol) = make_float2(v2, v3);
            } else {
                __half* C = (__half*)Cout;
                *(__half2*)(C + ((size_t)e * BB + row0) * (size_t)N + gcol) =
                    __floats2half2_rn(v0, v1);
                *(__half2*)(C + ((size_t)e * BB + row1) * (size_t)N + gcol) =
                    __floats2half2_rn(v2, v3);
            }
        }
    }
}

// ---------------------------------------------------------------------------
// K3: gating logits + softmax + top-2
// ---------------------------------------------------------------------------
__global__ void gate_kernel(const float* __restrict__ gw2,
                            const float* __restrict__ gb2,
                            float* __restrict__ gate_out) {
    int warp = threadIdx.x >> 5, lane = threadIdx.x & 31;
    int b = blockIdx.x * 8 + warp;
    const float* g1 = g_g1 + (size_t)b * GH;
    float logit[EE];
    #pragma unroll
    for (int e = 0; e < EE; e++) {
        float acc = 0.f;
        for (int k = lane; k < GH; k += 32) acc += g1[k] * gw2[k * EE + e];
        #pragma unroll
        for (int o = 16; o; o >>= 1) acc += __shfl_xor_sync(0xffffffffu, acc, o);
        logit[e] = acc + gb2[e];
    }
    if (lane == 0) {
        float mx = logit[0];
        #pragma unroll
        for (int e = 1; e < EE; e++) mx = fmaxf(mx, logit[e]);
        float p[EE]; float sum = 0.f;
        #pragma unroll
        for (int e = 0; e < EE; e++) { p[e] = expf(logit[e] - mx); sum += p[e]; }
        float invs = 1.0f / sum;
        #pragma unroll
        for (int e = 0; e < EE; e++) {
            p[e] *= invs;
            gate_out[(size_t)b * EE + e] = p[e];
        }
        int i0 = 0;
        #pragma unroll
        for (int e = 1; e < EE; e++) if (p[e] > p[i0]) i0 = e;
        int i1 = (i0 == 0) ? 1 : 0;
        #pragma unroll
        for (int e = 0; e < EE; e++) if (e != i0 && p[e] > p[i1]) i1 = e;
        float w0 = p[i0], w1 = p[i1], s = w0 + w1;
        g_w[b * 2 + 0] = w0 / s;
        g_w[b * 2 + 1] = w1 / s;
        g_i[b * 2 + 0] = i0;
        g_i[b * 2 + 1] = i1;
    }
}

// ---------------------------------------------------------------------------
// K6: weighted combine of top-2 expert outputs
// ---------------------------------------------------------------------------
__global__ void combine_kernel(const float* __restrict__ eo, float* __restrict__ out) {
    int b = blockIdx.x;
    int i0 = g_i[b * 2], i1 = g_i[b * 2 + 1];
    float w0 = g_w[b * 2], w1 = g_w[b * 2 + 1];
    const float* r0 = eo + (size_t)b * EE * DD + (size_t)i0 * DD;
    const float* r1 = eo + (size_t)b * EE * DD + (size_t)i1 * DD;
    float* o = out + (size_t)b * DD;
    for (int d = threadIdx.x; d < DD; d += blockDim.x)
        o[d] = w0 * r0[d] + w1 * r1[d];
}

// ---------------------------------------------------------------------------
extern "C" void kernel_launch(void* const* d_in, const int* in_sizes, int n_in,
                              void* d_out, int out_size) {
    const float* pooler   = (const float*)d_in[0];
    const float* ln_gamma = (const float*)d_in[1];
    const float* ln_beta  = (const float*)d_in[2];
    const float* gw1      = (const float*)d_in[3];
    const float* gb1      = (const float*)d_in[4];
    const float* gw2      = (const float*)d_in[5];
    const float* gb2      = (const float*)d_in[6];
    const float* ew1      = (const float*)d_in[7];
    const float* eb1      = (const float*)d_in[8];
    const float* ew2      = (const float*)d_in[9];
    const float* eb2      = (const float*)d_in[10];

    float* out        = (float*)d_out;
    float* out_result = out;                          // [B, D]
    float* out_gate   = out + (size_t)BB * DD;        // [B, E]
    float* out_eo     = out_gate + (size_t)BB * EE;   // [B, E, D]

    float  *g1_ptr;
    __half *ht_ptr, *htl_ptr, *hid_ptr, *w1t_ptr, *w2t_ptr, *gw1h_ptr, *gw1l_ptr;
    cudaGetSymbolAddress((void**)&ht_ptr,   g_ht);
    cudaGetSymbolAddress((void**)&htl_ptr,  g_htl);
    cudaGetSymbolAddress((void**)&g1_ptr,   g_g1);
    cudaGetSymbolAddress((void**)&hid_ptr,  g_hid);
    cudaGetSymbolAddress((void**)&w1t_ptr,  g_w1t);
    cudaGetSymbolAddress((void**)&w2t_ptr,  g_w2t);
    cudaGetSymbolAddress((void**)&gw1h_ptr, g_gw1h);
    cudaGetSymbolAddress((void**)&gw1l_ptr, g_gw1l);

    const int SMEM_E = 3 * 49152;   // 144 KB (expert GEMMs)
    const int SMEM_G = 3 * 65536;   // 192 KB (gate split GEMM)
    cudaFuncSetAttribute(hgemm256<DD, HH, true,  false>,
                         cudaFuncAttributeMaxDynamicSharedMemorySize, SMEM_E);
    cudaFuncSetAttribute(hgemm256<HH, DD, false, true>,
                         cudaFuncAttributeMaxDynamicSharedMemorySize, SMEM_E);
    cudaFuncSetAttribute(hgemm_gate,
                         cudaFuncAttributeMaxDynamicSharedMemorySize, SMEM_G);

    // 1) LayerNorm (hi/lo halves)
    ln_kernel<<<BB, 256>>>(pooler, ln_gamma, ln_beta);

    // 1b) weight transposes to K-major half (+ split for gw1)
    {
        dim3 blk(32, 8);
        transpose_h_kernel<<<dim3(HH / 32, DD / 32, EE), blk>>>(ew1, w1t_ptr, DD, HH);
        transpose_h_kernel<<<dim3(DD / 32, HH / 32, EE), blk>>>(ew2, w2t_ptr, HH, DD);
        transpose_split_kernel<<<dim3(GH / 32, DD / 32, 1), blk>>>(gw1, gw1h_ptr, gw1l_ptr, DD, GH);
    }

    // 2) gating hidden (split-fp16, fp32-faithful): g1 = gelu(h @ gw1 + gb1)
    hgemm_gate<<<dim3(GH / 128, BB / 128, 1), 256, SMEM_G>>>(
        ht_ptr, htl_ptr, gw1h_ptr, gw1l_ptr, gb1, g1_ptr);

    // 3) gating logits + softmax + top2
    gate_kernel<<<BB / 8, 256>>>(gw2, gb2, out_gate);

    // 4) expert hidden (fp16 mma): hid[e] = half(gelu(h @ ew1[e] + eb1[e]))
    hgemm256<DD, HH, true, false><<<dim3(HH / 256, BB / 128, EE), 256, SMEM_E>>>(
        ht_ptr, 0, w1t_ptr, eb1, hid_ptr);

    // 5) expert outputs (fp16 mma): eo[:,e,:] = hid[e] @ ew2[e] + eb2[e]
    hgemm256<HH, DD, false, true><<<dim3(DD / 256, BB / 128, EE), 256, SMEM_E>>>(
        hid_ptr, (size_t)BB * HH, w2t_ptr, eb2, out_eo);

    // 6) combine top-2
    combine_kernel<<<BB, 256>>>(out_eo, out_result);
}

// round 9
// speedup vs baseline: 1.1208x; 1.1208x over previous
#include <cuda_runtime.h>
#include <cuda_fp16.h>
#include <math.h>
#include <stdint.h>

#define BB 8192
#define DD 768
#define GH 384
#define EE 8
#define HH 3072
#define LN_EPS 1e-5f

// ---------------- scratch (static device globals) ----------------
__device__ __half g_ht [(size_t)BB * DD];          // LN output, half hi
__device__ __half g_htl[(size_t)BB * DD];          // LN output, half lo
__device__ float  g_g1 [(size_t)BB * GH];          // gating hidden (fp32-faithful)
__device__ __half g_hid[(size_t)EE * BB * HH];     // expert hidden, half
__device__ __half g_w1t[(size_t)EE * HH * DD];     // ew1^T [e][H][D], half (K-major)
__device__ __half g_w2t[(size_t)EE * DD * HH];     // ew2^T [e][D][H], half (K-major)
__device__ __half g_gw1h[(size_t)GH * DD];         // gw1^T hi [Gh][D]
__device__ __half g_gw1l[(size_t)GH * DD];         // gw1^T lo [Gh][D]
__device__ float  g_w  [(size_t)BB * 2];
__device__ int    g_i  [(size_t)BB * 2];

// ---------------- helpers ----------------
__device__ __forceinline__ float gelu_erf(float x) {
    return 0.5f * x * (1.0f + erff(x * 0.70710678118654752f));
}
__device__ __forceinline__ uint32_t s2u(const void* p) {
    uint32_t a;
    asm("{ .reg .u64 t; cvta.to.shared.u64 t, %1; cvt.u32.u64 %0, t; }" : "=r"(a) : "l"(p));
    return a;
}

#define SWZ(off) ((uint32_t)(off) ^ (((uint32_t)(off) >> 3) & 0x70u))

#define CPA16(dst, src) \
    asm volatile("cp.async.cg.shared.global [%0], [%1], 16;" :: "r"(dst), "l"(src))
#define CPCOMMIT() asm volatile("cp.async.commit_group;" ::: "memory")
#define CPWAIT0()  asm volatile("cp.async.wait_group 0;" ::: "memory")
#define CPWAIT1()  asm volatile("cp.async.wait_group 1;" ::: "memory")

#define LDSM4(r, addr) \
    asm volatile("ldmatrix.sync.aligned.m8n8.x4.shared.b16 {%0,%1,%2,%3}, [%4];" \
        : "=r"((r)[0]), "=r"((r)[1]), "=r"((r)[2]), "=r"((r)[3]) : "r"(addr))

__device__ __forceinline__ void mma_f16(float c[4], const uint32_t a[4],
                                        uint32_t b0, uint32_t b1) {
    asm volatile(
        "mma.sync.aligned.m16n8k16.row.col.f32.f16.f16.f32 "
        "{%0,%1,%2,%3}, {%4,%5,%6,%7}, {%8,%9}, {%0,%1,%2,%3};"
        : "+f"(c[0]), "+f"(c[1]), "+f"(c[2]), "+f"(c[3])
        : "r"(a[0]), "r"(a[1]), "r"(a[2]), "r"(a[3]), "r"(b0), "r"(b1));
}

// ---------------------------------------------------------------------------
// K1: LayerNorm -> g_ht (hi) + g_htl (lo)
// ---------------------------------------------------------------------------
__global__ void ln_kernel(const float* __restrict__ x,
                          const float* __restrict__ gamma,
                          const float* __restrict__ beta) {
    int b = blockIdx.x;
    const float* row = x + (size_t)b * DD;
    float s = 0.f, ss = 0.f;
    for (int d = threadIdx.x; d < DD; d += blockDim.x) {
        float v = row[d];
        s += v; ss += v * v;
    }
    #pragma unroll
    for (int o = 16; o; o >>= 1) {
        s  += __shfl_xor_sync(0xffffffffu, s, o);
        ss += __shfl_xor_sync(0xffffffffu, ss, o);
    }
    __shared__ float rs[8], rss[8];
    int w = threadIdx.x >> 5, l = threadIdx.x & 31;
    if (l == 0) { rs[w] = s; rss[w] = ss; }
    __syncthreads();
    if (w == 0) {
        s  = (l < (blockDim.x >> 5)) ? rs[l]  : 0.f;
        ss = (l < (blockDim.x >> 5)) ? rss[l] : 0.f;
        #pragma unroll
        for (int o = 4; o; o >>= 1) {
            s  += __shfl_xor_sync(0xffffffffu, s, o);
            ss += __shfl_xor_sync(0xffffffffu, ss, o);
        }
        if (l == 0) { rs[0] = s; rss[0] = ss; }
    }
    __syncthreads();
    float mu  = rs[0] * (1.0f / DD);
    float var = rss[0] * (1.0f / DD) - mu * mu;
    float inv = rsqrtf(var + LN_EPS);
    for (int d = threadIdx.x; d < DD; d += blockDim.x) {
        float v = (row[d] - mu) * inv * gamma[d] + beta[d];
        __half hi = __float2half_rn(v);
        g_ht [(size_t)b * DD + d] = hi;
        g_htl[(size_t)b * DD + d] = __float2half_rn(v - __half2float(hi));
    }
}

// ---------------------------------------------------------------------------
// Weight transpose + fp32->half: src fp32 [e][R][C] -> dst half [e][C][R]
// ---------------------------------------------------------------------------
__global__ void transpose_h_kernel(const float* __restrict__ src,
                                   __half* __restrict__ dst, int R, int C) {
    __shared__ float t[32][33];
    int e = blockIdx.z;
    src += (size_t)e * R * C;
    dst += (size_t)e * R * C;
    int c0 = blockIdx.x * 32, r0 = blockIdx.y * 32;
    #pragma unroll
    for (int j = 0; j < 32; j += 8)
        t[threadIdx.y + j][threadIdx.x] =
            src[(size_t)(r0 + threadIdx.y + j) * C + c0 + threadIdx.x];
    __syncthreads();
    #pragma unroll
    for (int j = 0; j < 32; j += 8)
        dst[(size_t)(c0 + threadIdx.y + j) * R + r0 + threadIdx.x] =
            __float2half_rn(t[threadIdx.x][threadIdx.y + j]);
}

// Transpose + hi/lo split: src fp32 [R][C] -> hi/lo half [C][R]
__global__ void transpose_split_kernel(const float* __restrict__ src,
                                       __half* __restrict__ dh,
                                       __half* __restrict__ dl, int R, int C) {
    __shared__ float t[32][33];
    int c0 = blockIdx.x * 32, r0 = blockIdx.y * 32;
    #pragma unroll
    for (int j = 0; j < 32; j += 8)
        t[threadIdx.y + j][threadIdx.x] =
            src[(size_t)(r0 + threadIdx.y + j) * C + c0 + threadIdx.x];
    __syncthreads();
    #pragma unroll
    for (int j = 0; j < 32; j += 8) {
        float v = t[threadIdx.x][threadIdx.y + j];
        __half hi = __float2half_rn(v);
        size_t idx = (size_t)(c0 + threadIdx.y + j) * R + r0 + threadIdx.x;
        dh[idx] = hi;
        dl[idx] = __float2half_rn(v - __half2float(hi));
    }
}

// ---------------------------------------------------------------------------
// Split-fp16 gate GEMM: g1 = gelu((Ah+Al) @ (Bh+Bl)^T + gb1), fp32-faithful.
// M=BB, N=GH, K=DD. CTA 128x128, BK=64, 3-stage. acc = AhBh + AhBl + AlBh.
// ---------------------------------------------------------------------------
__global__ __launch_bounds__(256, 1)
void hgemm_gate(const __half* __restrict__ Ah, const __half* __restrict__ Al,
                const __half* __restrict__ Bh, const __half* __restrict__ Bl,
                const float* __restrict__ bias, float* __restrict__ C) {
    constexpr int K = DD, BK = 64, NIT = K / BK;
    constexpr int TB = 128 * 128;            // 16 KB per tile
    constexpr int STAGE_BYTES = 4 * TB;      // 64 KB
    constexpr int STAGES = 3;

    extern __shared__ char smem[];
    const int n0 = blockIdx.x * 128;
    const int m0 = blockIdx.y * 128;

    const int tid   = threadIdx.x;
    const int warp  = tid >> 5;
    const int lane  = tid & 31;
    const int warpM = warp >> 2;
    const int warpN = warp & 3;

    const uint32_t sbase = s2u(smem);

    auto load_stage = [&](int s, int k0) {
        uint32_t aH = sbase + (uint32_t)s * STAGE_BYTES;
        uint32_t aL = aH + TB, bH = aH + 2 * TB, bL = aH + 3 * TB;
        #pragma unroll
        for (int t = 0; t < 4; t++) {
            int id = tid + t * 256;
            int row = id >> 3, c = id & 7;
            uint32_t o = SWZ(row * 128 + c * 16);
            CPA16(aH + o, Ah + (size_t)(m0 + row) * K + k0 + c * 8);
            CPA16(aL + o, Al + (size_t)(m0 + row) * K + k0 + c * 8);
            CPA16(bH + o, Bh + (size_t)(n0 + row) * K + k0 + c * 8);
            CPA16(bL + o, Bl + (size_t)(n0 + row) * K + k0 + c * 8);
        }
    };

    load_stage(0, 0);   CPCOMMIT();
    load_stage(1, BK);  CPCOMMIT();

    float acc[4][4][4] = {};

    for (int i = 0; i < NIT; i++) {
        if (i + 1 < NIT) { CPWAIT1(); } else { CPWAIT0(); }
        __syncthreads();
        if (i + 2 < NIT) { load_stage((i + 2) % STAGES, (i + 2) * BK); CPCOMMIT(); }

        const uint32_t aH = sbase + (uint32_t)(i % STAGES) * STAGE_BYTES;
        const uint32_t aL = aH + TB, bH = aH + 2 * TB, bL = aH + 3 * TB;

        #pragma unroll
        for (int ks = 0; ks < 4; ks++) {
            uint32_t afh[4][4], afl[4][4], bfh[2][4], bfl[2][4];
            const int c = ks * 2 + (lane >> 4);
            #pragma unroll
            for (int ii = 0; ii < 4; ii++) {
                int row = warpM * 64 + ii * 16 + (lane & 15);
                uint32_t o = SWZ(row * 128 + c * 16);
                LDSM4(afh[ii], aH + o);
                LDSM4(afl[ii], aL + o);
            }
            #pragma unroll
            for (int jp = 0; jp < 2; jp++) {
                int row = warpN * 32 + jp * 16 + (lane & 15);
                uint32_t o = SWZ(row * 128 + c * 16);
                LDSM4(bfh[jp], bH + o);
                LDSM4(bfl[jp], bL + o);
            }
            #pragma unroll
            for (int ii = 0; ii < 4; ii++) {
                #pragma unroll
                for (int jp = 0; jp < 2; jp++) {
                    mma_f16(acc[ii][jp * 2 + 0], afh[ii], bfh[jp][0], bfh[jp][2]);
                    mma_f16(acc[ii][jp * 2 + 1], afh[ii], bfh[jp][1], bfh[jp][3]);
                    mma_f16(acc[ii][jp * 2 + 0], afh[ii], bfl[jp][0], bfl[jp][2]);
                    mma_f16(acc[ii][jp * 2 + 1], afh[ii], bfl[jp][1], bfl[jp][3]);
                    mma_f16(acc[ii][jp * 2 + 0], afl[ii], bfh[jp][0], bfh[jp][2]);
                    mma_f16(acc[ii][jp * 2 + 1], afl[ii], bfh[jp][1], bfh[jp][3]);
                }
            }
        }
    }

    const int r  = lane >> 2;
    const int c2 = (lane & 3) * 2;
    #pragma unroll
    for (int ii = 0; ii < 4; ii++) {
        int row0 = m0 + warpM * 64 + ii * 16 + r;
        int row1 = row0 + 8;
        #pragma unroll
        for (int j = 0; j < 4; j++) {
            int gcol = n0 + warpN * 32 + j * 8 + c2;
            float b0 = bias[gcol], b1 = bias[gcol + 1];
            float v0 = gelu_erf(acc[ii][j][0] + b0);
            float v1 = gelu_erf(acc[ii][j][1] + b1);
            float v2 = gelu_erf(acc[ii][j][2] + b0);
            float v3 = gelu_erf(acc[ii][j][3] + b1);
            *(float2*)(C + (size_t)row0 * GH + gcol) = make_float2(v0, v1);
            *(float2*)(C + (size_t)row1 * GH + gcol) = make_float2(v2, v3);
        }
    }
}

// ---------------------------------------------------------------------------
// Expert fp16 GEMM (R7 config): CTA 128x128, warp tile 64x32, BK=64,
// 3-stage cp.async, 2 CTAs/SM. A half [e][M][K]; Bt half [e][N][K] K-major.
// ---------------------------------------------------------------------------
template <int K, int N, bool GELU, bool EOUT>
__global__ __launch_bounds__(256, 2)
void hgemm(const __half* __restrict__ A, size_t aStride,
           const __half* __restrict__ Bt,
           const float* __restrict__ bias,
           void* __restrict__ Cout) {
    constexpr int BK = 64;
    constexpr int NIT = K / BK;
    constexpr int ABYTES = 128 * 128;      // 16 KB per operand tile
    constexpr int STAGE_BYTES = 2 * ABYTES;
    constexpr int STAGES = 3;

    extern __shared__ char smem[];
    const int e  = blockIdx.z;
    const int n0 = blockIdx.x * 128;
    const int m0 = blockIdx.y * 128;
    A    += (size_t)e * aStride;
    Bt   += (size_t)e * (size_t)N * K;
    bias += (size_t)e * N;

    const int tid   = threadIdx.x;
    const int warp  = tid >> 5;
    const int lane  = tid & 31;
    const int warpM = warp >> 2;
    const int warpN = warp & 3;

    const uint32_t sbase = s2u(smem);

    auto load_stage = [&](int s, int k0) {
        uint32_t aB = sbase + (uint32_t)s * STAGE_BYTES;
        uint32_t bB = aB + ABYTES;
        #pragma unroll
        for (int t = 0; t < 4; t++) {
            int id = tid + t * 256;
            int row = id >> 3, c = id & 7;
            CPA16(aB + SWZ(row * 128 + c * 16), A + (size_t)(m0 + row) * K + k0 + c * 8);
        }
        #pragma unroll
        for (int t = 0; t < 4; t++) {
            int id = tid + t * 256;
            int row = id >> 3, c = id & 7;
            CPA16(bB + SWZ(row * 128 + c * 16), Bt + (size_t)(n0 + row) * K + k0 + c * 8);
        }
    };

    load_stage(0, 0);   CPCOMMIT();
    load_stage(1, BK);  CPCOMMIT();

    float acc[4][4][4] = {};

    for (int i = 0; i < NIT; i++) {
        if (i + 1 < NIT) { CPWAIT1(); } else { CPWAIT0(); }
        __syncthreads();

        if (i + 2 < NIT) {
            load_stage((i + 2) % STAGES, (i + 2) * BK);
            CPCOMMIT();
        }

        const int s = i % STAGES;
        const uint32_t aB = sbase + (uint32_t)s * STAGE_BYTES;
        const uint32_t bB = aB + ABYTES;

        #pragma unroll
        for (int ks = 0; ks < 4; ks++) {
            uint32_t afr[4][4], bfr[2][4];
            const int c = ks * 2 + (lane >> 4);
            #pragma unroll
            for (int ii = 0; ii < 4; ii++) {
                int row = warpM * 64 + ii * 16 + (lane & 15);
                LDSM4(afr[ii], aB + SWZ(row * 128 + c * 16));
            }
            #pragma unroll
            for (int jp = 0; jp < 2; jp++) {
                int row = warpN * 32 + jp * 16 + (lane & 15);
                LDSM4(bfr[jp], bB + SWZ(row * 128 + c * 16));
            }
            #pragma unroll
            for (int ii = 0; ii < 4; ii++) {
                #pragma unroll
                for (int jp = 0; jp < 2; jp++) {
                    mma_f16(acc[ii][jp * 2 + 0], afr[ii], bfr[jp][0], bfr[jp][2]);
                    mma_f16(acc[ii][jp * 2 + 1], afr[ii], bfr[jp][1], bfr[jp][3]);
                }
            }
        }
    }

    // epilogue
    const int r  = lane >> 2;
    const int c2 = (lane & 3) * 2;
    #pragma unroll
    for (int ii = 0; ii < 4; ii++) {
        int row0 = m0 + warpM * 64 + ii * 16 + r;
        int row1 = row0 + 8;
        #pragma unroll
        for (int j = 0; j < 4; j++) {
            int gcol = n0 + warpN * 32 + j * 8 + c2;
            float b0 = bias[gcol], b1 = bias[gcol + 1];
            float v0 = acc[ii][j][0] + b0;
            float v1 = acc[ii][j][1] + b1;
            float v2 = acc[ii][j][2] + b0;
            float v3 = acc[ii][j][3] + b1;
            if (GELU) {
                v0 = gelu_erf(v0); v1 = gelu_erf(v1);
                v2 = gelu_erf(v2); v3 = gelu_erf(v3);
            }
            if (EOUT) {
                float* C = (float*)Cout;
                *(float2*)(C + ((size_t)row0 * EE + e) * DD + gcol) = make_float2(v0, v1);
                *(float2*)(C + ((size_t)row1 * EE + e) * DD + gcol) = make_float2(v2, v3);
            } else {
                __half* C = (__half*)Cout;
                *(__half2*)(C + ((size_t)e * BB + row0) * (size_t)N + gcol) =
                    __floats2half2_rn(v0, v1);
                *(__half2*)(C + ((size_t)e * BB + row1) * (size_t)N + gcol) =
                    __floats2half2_rn(v2, v3);
            }
        }
    }
}

// ---------------------------------------------------------------------------
// K3: gating logits + softmax + top-2
// ---------------------------------------------------------------------------
__global__ void gate_kernel(const float* __restrict__ gw2,
                            const float* __restrict__ gb2,
                            float* __restrict__ gate_out) {
    int warp = threadIdx.x >> 5, lane = threadIdx.x & 31;
    int b = blockIdx.x * 8 + warp;
    const float* g1 = g_g1 + (size_t)b * GH;
    float logit[EE];
    #pragma unroll
    for (int e = 0; e < EE; e++) {
        float acc = 0.f;
        for (int k = lane; k < GH; k += 32) acc += g1[k] * gw2[k * EE + e];
        #pragma unroll
        for (int o = 16; o; o >>= 1) acc += __shfl_xor_sync(0xffffffffu, acc, o);
        logit[e] = acc + gb2[e];
    }
    if (lane == 0) {
        float mx = logit[0];
        #pragma unroll
        for (int e = 1; e < EE; e++) mx = fmaxf(mx, logit[e]);
        float p[EE]; float sum = 0.f;
        #pragma unroll
        for (int e = 0; e < EE; e++) { p[e] = expf(logit[e] - mx); sum += p[e]; }
        float invs = 1.0f / sum;
        #pragma unroll
        for (int e = 0; e < EE; e++) {
            p[e] *= invs;
            gate_out[(size_t)b * EE + e] = p[e];
        }
        int i0 = 0;
        #pragma unroll
        for (int e = 1; e < EE; e++) if (p[e] > p[i0]) i0 = e;
        int i1 = (i0 == 0) ? 1 : 0;
        #pragma unroll
        for (int e = 0; e < EE; e++) if (e != i0 && p[e] > p[i1]) i1 = e;
        float w0 = p[i0], w1 = p[i1], s = w0 + w1;
        g_w[b * 2 + 0] = w0 / s;
        g_w[b * 2 + 1] = w1 / s;
        g_i[b * 2 + 0] = i0;
        g_i[b * 2 + 1] = i1;
    }
}

// ---------------------------------------------------------------------------
// K6: weighted combine of top-2 expert outputs
// ---------------------------------------------------------------------------
__global__ void combine_kernel(const float* __restrict__ eo, float* __restrict__ out) {
    int b = blockIdx.x;
    int i0 = g_i[b * 2], i1 = g_i[b * 2 + 1];
    float w0 = g_w[b * 2], w1 = g_w[b * 2 + 1];
    const float* r0 = eo + (size_t)b * EE * DD + (size_t)i0 * DD;
    const float* r1 = eo + (size_t)b * EE * DD + (size_t)i1 * DD;
    float* o = out + (size_t)b * DD;
    for (int d = threadIdx.x; d < DD; d += blockDim.x)
        o[d] = w0 * r0[d] + w1 * r1[d];
}

// ---------------------------------------------------------------------------
extern "C" void kernel_launch(void* const* d_in, const int* in_sizes, int n_in,
                              void* d_out, int out_size) {
    const float* pooler   = (const float*)d_in[0];
    const float* ln_gamma = (const float*)d_in[1];
    const float* ln_beta  = (const float*)d_in[2];
    const float* gw1      = (const float*)d_in[3];
    const float* gb1      = (const float*)d_in[4];
    const float* gw2      = (const float*)d_in[5];
    const float* gb2      = (const float*)d_in[6];
    const float* ew1      = (const float*)d_in[7];
    const float* eb1      = (const float*)d_in[8];
    const float* ew2      = (const float*)d_in[9];
    const float* eb2      = (const float*)d_in[10];

    float* out        = (float*)d_out;
    float* out_result = out;                          // [B, D]
    float* out_gate   = out + (size_t)BB * DD;        // [B, E]
    float* out_eo     = out_gate + (size_t)BB * EE;   // [B, E, D]

    float  *g1_ptr;
    __half *ht_ptr, *htl_ptr, *hid_ptr, *w1t_ptr, *w2t_ptr, *gw1h_ptr, *gw1l_ptr;
    cudaGetSymbolAddress((void**)&ht_ptr,   g_ht);
    cudaGetSymbolAddress((void**)&htl_ptr,  g_htl);
    cudaGetSymbolAddress((void**)&g1_ptr,   g_g1);
    cudaGetSymbolAddress((void**)&hid_ptr,  g_hid);
    cudaGetSymbolAddress((void**)&w1t_ptr,  g_w1t);
    cudaGetSymbolAddress((void**)&w2t_ptr,  g_w2t);
    cudaGetSymbolAddress((void**)&gw1h_ptr, g_gw1h);
    cudaGetSymbolAddress((void**)&gw1l_ptr, g_gw1l);

    const int SMEM_E = 3 * 32768;   // 96 KB  (expert GEMMs, 2 CTAs/SM)
    const int SMEM_G = 3 * 65536;   // 192 KB (gate split GEMM)
    cudaFuncSetAttribute(hgemm<DD, HH, true,  false>,
                         cudaFuncAttributeMaxDynamicSharedMemorySize, SMEM_E);
    cudaFuncSetAttribute(hgemm<HH, DD, false, true>,
                         cudaFuncAttributeMaxDynamicSharedMemorySize, SMEM_E);
    cudaFuncSetAttribute(hgemm_gate,
                         cudaFuncAttributeMaxDynamicSharedMemorySize, SMEM_G);

    // 1) LayerNorm (hi/lo halves)
    ln_kernel<<<BB, 256>>>(pooler, ln_gamma, ln_beta);

    // 1b) weight transposes to K-major half (+ split for gw1)
    {
        dim3 blk(32, 8);
        transpose_h_kernel<<<dim3(HH / 32, DD / 32, EE), blk>>>(ew1, w1t_ptr, DD, HH);
        transpose_h_kernel<<<dim3(DD / 32, HH / 32, EE), blk>>>(ew2, w2t_ptr, HH, DD);
        transpose_split_kernel<<<dim3(GH / 32, DD / 32, 1), blk>>>(gw1, gw1h_ptr, gw1l_ptr, DD, GH);
    }

    // 2) gating hidden (split-fp16, fp32-faithful): g1 = gelu(h @ gw1 + gb1)
    hgemm_gate<<<dim3(GH / 128, BB / 128, 1), 256, SMEM_G>>>(
        ht_ptr, htl_ptr, gw1h_ptr, gw1l_ptr, gb1, g1_ptr);

    // 3) gating logits + softmax + top2
    gate_kernel<<<BB / 8, 256>>>(gw2, gb2, out_gate);

    // 4) expert hidden (fp16 mma): hid[e] = half(gelu(h @ ew1[e] + eb1[e]))
    hgemm<DD, HH, true, false><<<dim3(HH / 128, BB / 128, EE), 256, SMEM_E>>>(
        ht_ptr, 0, w1t_ptr, eb1, hid_ptr);

    // 5) expert outputs (fp16 mma): eo[:,e,:] = hid[e] @ ew2[e] + eb2[e]
    hgemm<HH, DD, false, true><<<dim3(DD / 128, BB / 128, EE), 256, SMEM_E>>>(
        hid_ptr, (size_t)BB * HH, w2t_ptr, eb2, out_eo);

    // 6) combine top-2
    combine_kernel<<<BB, 256>>>(out_eo, out_result);
}